// round 12
// baseline (speedup 1.0000x reference)
#include <cuda_runtime.h>
#include <cuda_bf16.h>
#include <cuda_fp16.h>
#include <math.h>
#include <stdint.h>

// Problem constants
#define N_TOK  8192
#define D_INF  1024
#define D_HIDF 4096
#define D_OUTF 1024
#define NE     8
#define TOPK   2
#define NROWS  (N_TOK * TOPK)

#define LO_SCALE     2048.0f
#define LO_INV_SCALE (1.0f / 2048.0f)

// ---------------- scratch (__device__ globals; allocation-free rule) --------
__device__ __align__(256) __half g_xhi[(size_t)N_TOK * D_INF];
__device__ __align__(256) __half g_xlo[(size_t)N_TOK * D_INF];   // scaled by 2048
__device__ __align__(256) __half g_w1t[(size_t)NE * D_HIDF * D_INF];  // [E][Nhid][Kin]
__device__ __align__(256) __half g_w2t[(size_t)NE * D_OUTF * D_HIDF]; // [E][Nout][Khid]
__device__ __align__(256) __half g_hhi[(size_t)NROWS * D_HIDF];
__device__ __align__(256) __half g_hlo[(size_t)NROWS * D_HIDF];  // scaled by 2048
__device__ __align__(256) float g_partial[(size_t)NROWS * D_OUTF];
__device__ int   g_counts[NE];
__device__ int   g_offsets[NE + 1];
__device__ int   g_cursor[NE];
__device__ int   g_row_token[NROWS];
__device__ int   g_token_row[NROWS];
__device__ int   g_e_of[NROWS];
__device__ float g_w_of[NROWS];

// ---------------- PTX helpers (base sm_103 only; NO 'a' features) -----------
__device__ __forceinline__ uint32_t smem_u32(const void* p) {
    uint32_t a;
    asm("{ .reg .u64 t; cvta.to.shared.u64 t, %1; cvt.u32.u64 %0, t; }"
        : "=r"(a) : "l"(p));
    return a;
}
__device__ __forceinline__ void cp16(uint32_t dst, const void* src) {
    unsigned long long g = (unsigned long long)__cvta_generic_to_global(src);
    asm volatile("cp.async.cg.shared.global [%0], [%1], 16;" :: "r"(dst), "l"(g));
}
#define CP_COMMIT() asm volatile("cp.async.commit_group;" ::: "memory")
template <int Np> __device__ __forceinline__ void cp_wait() {
    asm volatile("cp.async.wait_group %0;" :: "n"(Np) : "memory");
}
__device__ __forceinline__ void ldsm_x4(uint32_t& r0, uint32_t& r1, uint32_t& r2,
                                        uint32_t& r3, uint32_t addr) {
    asm volatile("ldmatrix.sync.aligned.m8n8.x4.shared.b16 {%0,%1,%2,%3}, [%4];"
                 : "=r"(r0), "=r"(r1), "=r"(r2), "=r"(r3) : "r"(addr));
}
// f32-accumulator fp16 MMA (hi pass)
__device__ __forceinline__ void mma_f16(float* c, const uint32_t* a, uint32_t b0,
                                        uint32_t b1) {
    asm volatile(
        "mma.sync.aligned.m16n8k16.row.col.f32.f16.f16.f32 "
        "{%0,%1,%2,%3}, {%4,%5,%6,%7}, {%8,%9}, {%0,%1,%2,%3};"
        : "+f"(c[0]), "+f"(c[1]), "+f"(c[2]), "+f"(c[3])
        : "r"(a[0]), "r"(a[1]), "r"(a[2]), "r"(a[3]), "r"(b0), "r"(b1));
}
// f16-accumulator fp16 MMA (lo pass; 2x rate if f32-acc is de-rated)
__device__ __forceinline__ void mma_f16h(uint32_t* c, const uint32_t* a, uint32_t b0,
                                         uint32_t b1) {
    asm volatile(
        "mma.sync.aligned.m16n8k16.row.col.f16.f16.f16.f16 "
        "{%0,%1}, {%2,%3,%4,%5}, {%6,%7}, {%0,%1};"
        : "+r"(c[0]), "+r"(c[1])
        : "r"(a[0]), "r"(a[1]), "r"(a[2]), "r"(a[3]), "r"(b0), "r"(b1));
}
__device__ __forceinline__ uint32_t hpack(__half a, __half b) {
    return (uint32_t)__half_as_ushort(a) | ((uint32_t)__half_as_ushort(b) << 16);
}

// ---------------- kernel 0: reset --------------------------------------------
__global__ void reset_kernel() {
    int t = threadIdx.x;
    if (t < NE) g_counts[t] = 0;
}

// ---------------- kernel 1: gating -------------------------------------------
__global__ __launch_bounds__(256) void gating_kernel(
    const float* __restrict__ x, const float* __restrict__ Wg,
    const float* __restrict__ bg)
{
    int gwarp = (blockIdx.x * blockDim.x + threadIdx.x) >> 5;
    int lane  = threadIdx.x & 31;
    if (gwarp >= N_TOK) return;
    const float* xr = x + (size_t)gwarp * D_INF;

    float acc[NE];
#pragma unroll
    for (int e = 0; e < NE; e++) acc[e] = 0.f;
    for (int k = lane; k < D_INF; k += 32) {
        float xv = xr[k];
        const float* wgr = Wg + (size_t)k * NE;
#pragma unroll
        for (int e = 0; e < NE; e++) acc[e] = fmaf(xv, wgr[e], acc[e]);
    }
#pragma unroll
    for (int off = 16; off; off >>= 1)
#pragma unroll
        for (int e = 0; e < NE; e++)
            acc[e] += __shfl_xor_sync(0xffffffffu, acc[e], off);

    if (lane == 0) {
        float s[NE];
#pragma unroll
        for (int e = 0; e < NE; e++) s[e] = acc[e] + bg[e];
        float mx = s[0];
#pragma unroll
        for (int e = 1; e < NE; e++) mx = fmaxf(mx, s[e]);
        float p[NE], sum = 0.f;
#pragma unroll
        for (int e = 0; e < NE; e++) { p[e] = expf(s[e] - mx); sum += p[e]; }
        float inv = 1.0f / sum;
#pragma unroll
        for (int e = 0; e < NE; e++) p[e] *= inv;
        int e0 = 0;
#pragma unroll
        for (int e = 1; e < NE; e++) if (s[e] > s[e0]) e0 = e;
        int e1 = (e0 == 0) ? 1 : 0;
#pragma unroll
        for (int e = 0; e < NE; e++) if (e != e0 && s[e] > s[e1]) e1 = e;
        float denom = p[e0] + p[e1] + 1e-8f;
        int n = gwarp;
        g_e_of[2*n+0] = e0;  g_e_of[2*n+1] = e1;
        g_w_of[2*n+0] = p[e0] / denom;  g_w_of[2*n+1] = p[e1] / denom;
        atomicAdd(&g_counts[e0], 1);
        atomicAdd(&g_counts[e1], 1);
    }
}

// ---------------- kernel 2/3: scan + placement -------------------------------
__global__ void scan_kernel() {
    int o = 0;
#pragma unroll
    for (int e = 0; e < NE; e++) { g_offsets[e] = o; g_cursor[e] = o; o += g_counts[e]; }
    g_offsets[NE] = o;
}
__global__ void place_kernel() {
    int n = blockIdx.x * blockDim.x + threadIdx.x;
    if (n >= N_TOK) return;
#pragma unroll
    for (int s = 0; s < TOPK; s++) {
        int e = g_e_of[2*n+s];
        int r = atomicAdd(&g_cursor[e], 1);
        g_row_token[r] = n;
        g_token_row[2*n+s] = r;
    }
}

// ---------------- prepass: x -> fp16 hi + scaled lo ---------------------------
__global__ __launch_bounds__(256) void cvtx_kernel(const float* __restrict__ x) {
    size_t i = ((size_t)blockIdx.x * 256 + threadIdx.x) * 4;
    float4 v = *(const float4*)(x + i);
    __half h0 = __float2half_rn(v.x), h1 = __float2half_rn(v.y);
    __half h2 = __float2half_rn(v.z), h3 = __float2half_rn(v.w);
    __half l0 = __float2half_rn((v.x - __half2float(h0)) * LO_SCALE);
    __half l1 = __float2half_rn((v.y - __half2float(h1)) * LO_SCALE);
    __half l2 = __float2half_rn((v.z - __half2float(h2)) * LO_SCALE);
    __half l3 = __float2half_rn((v.w - __half2float(h3)) * LO_SCALE);
    uint2 hh, ll;
    hh.x = hpack(h0, h1); hh.y = hpack(h2, h3);
    ll.x = hpack(l0, l1); ll.y = hpack(l2, l3);
    *(uint2*)(g_xhi + i) = hh;
    *(uint2*)(g_xlo + i) = ll;
}

// ---------------- prepass: W [E][K][N] -> WT fp16 [E][N][K] -------------------
template <int K, int N, int WCH>
__global__ void tpose_kernel(const float* __restrict__ Wsrc) {
    __shared__ float t[32][33];
    int e  = blockIdx.z;
    int n0 = blockIdx.x * 32, k0 = blockIdx.y * 32;
    int tx = threadIdx.x, ty = threadIdx.y;  // 32 x 8
    const float* src = Wsrc + ((size_t)e * K + k0) * N + n0;
#pragma unroll
    for (int i = 0; i < 4; i++)
        t[ty + 8*i][tx] = src[(size_t)(ty + 8*i) * N + tx];
    __syncthreads();
    __half* T = (WCH == 1) ? g_w1t : g_w2t;
    size_t ob = ((size_t)e * N + n0) * K + k0;
#pragma unroll
    for (int i = 0; i < 4; i++) {
        float v = t[tx][ty + 8*i];
        T[ob + (size_t)(ty + 8*i) * K + tx] = __float2half_rn(v);
    }
}

// ---------------- grouped HMMA GEMM (fp16 hi/lo, f32/f16 dual-acc) ------------
// BM=128, BN=128, BK=64, 256 threads (8 warps, warp tile 64x32), 2-stage
// cp.async, 2 CTAs/SM. Stage rows: [0,128)=Ahi, [128,256)=Alo, [256,384)=B.
#define ROWP       144
#define STAGE_ROWS 384
#define STAGE_SZ   (STAGE_ROWS * ROWP)      // 55296
#define SMEM_DYN   (2 * STAGE_SZ + 128)     // 110720

template <int G>
__global__ __launch_bounds__(256, 2) void gemm_kernel(const float* __restrict__ bias_g) {
    constexpr int KD = (G == 1) ? D_INF : D_HIDF;
    constexpr int NT = (G == 1) ? D_HIDF : D_OUTF;
    constexpr int KT = KD / 64;

    const int e    = blockIdx.z;
    const int rbeg = g_offsets[e];
    const int rend = g_offsets[e + 1];
    const int m0   = rbeg + blockIdx.y * 128;
    if (m0 >= rend) return;
    const int n0   = blockIdx.x * 128;

    __shared__ float sbias[128];
    extern __shared__ char dsm[];
    const uint32_t dynb = (smem_u32(dsm) + 127u) & ~127u;

    const int tid  = threadIdx.x;
    const int wid  = tid >> 5;
    const int lane = tid & 31;

    if (tid < 128) sbias[tid] = bias_g[(size_t)e * NT + n0 + tid];

    const __half* ahi_g = (G == 1) ? g_xhi : g_hhi;
    const __half* alo_g = (G == 1) ? g_xlo : g_hlo;
    const __half* b_g   = (G == 1) ? g_w1t : g_w2t;

    // ---- loader geometry: 384 rows / 256 threads (row tid, + row 256+tid for tid<128)
    const __half* gsrc[2];
    uint32_t dstoff[2];
    const bool has2 = (tid < 128);
#pragma unroll
    for (int q = 0; q < 2; q++) {
        const int r = tid + 256 * q;        // q0: 0..255, q1: 256..383 (tid<128)
        if (r < 256) {                      // A rows (hi then lo)
            int gr = m0 + (r & 127);
            if (gr >= rend) gr = rbeg;      // valid garbage row; epilogue masks
            size_t rowb = (G == 1) ? (size_t)g_row_token[gr] * KD : (size_t)gr * KD;
            gsrc[q] = ((r < 128) ? ahi_g : alo_g) + rowb;
            dstoff[q] = (uint32_t)(r * ROWP);
        } else if (r < 384) {               // B rows
            const int br = r - 256;         // 0..127
            size_t rowb = ((size_t)e * NT + n0 + br) * KD;
            gsrc[q] = b_g + rowb;
            dstoff[q] = (uint32_t)(r * ROWP);
        } else {
            gsrc[q] = gsrc[0];              // unused (guarded by has2)
            dstoff[q] = dstoff[0];
        }
    }

    auto load_stage = [&](int kt, int stg) {
        const uint32_t sb = dynb + (uint32_t)stg * STAGE_SZ;
        const int k0 = kt * 64;
        {
            const __half* src = gsrc[0] + k0;
            const uint32_t dst = sb + dstoff[0];
#pragma unroll
            for (int c = 0; c < 8; c++) cp16(dst + c * 16, src + c * 8);
        }
        if (has2) {
            const __half* src = gsrc[1] + k0;
            const uint32_t dst = sb + dstoff[1];
#pragma unroll
            for (int c = 0; c < 8; c++) cp16(dst + c * 16, src + c * 8);
        }
        CP_COMMIT();
    };

    // ---- fragment address bases ----
    const int wm = (wid >> 2) * 64;     // warp M offset: 0,64
    const int wn = (wid & 3) * 32;      // warp N offset: 0,32,64,96
    const int mtx = lane >> 3;          // ldmatrix matrix id 0..3
    const int inr = lane & 7;
    // A x4 tile: matrices {m0-7 k0, m8-15 k0, m0-7 k8, m8-15 k8}
    const uint32_t aoff_hi = (uint32_t)((wm + (mtx & 1) * 8 + inr) * ROWP + (mtx >> 1) * 16);
    const uint32_t aoff_lo = aoff_hi + 128 * ROWP;
    // B x4 tile: matrices {n0-7 k0, n0-7 k8, n8-15 k0, n8-15 k8}
    const uint32_t boff = (uint32_t)((256 + wn + (mtx >> 1) * 8 + inr) * ROWP + (mtx & 1) * 16);

    float    acc[4][4][4];    // hi pass, f32 accumulators
    uint32_t acc16[4][4][2];  // lo pass, f16 accumulators (packed half2 x2)
#pragma unroll
    for (int i = 0; i < 4; i++)
#pragma unroll
        for (int j = 0; j < 4; j++) {
#pragma unroll
            for (int q = 0; q < 4; q++) acc[i][j][q] = 0.f;
            acc16[i][j][0] = 0u; acc16[i][j][1] = 0u;
        }

    load_stage(0, 0);

    for (int kt = 0; kt < KT; kt++) {
        cp_wait<0>();
        __syncthreads();   // stage kt visible; prior stage's consumers done
        if (kt + 1 < KT) load_stage(kt + 1, (kt + 1) & 1);

        const uint32_t sb = dynb + (uint32_t)(kt & 1) * STAGE_SZ;
#pragma unroll
        for (int ks = 0; ks < 4; ks++) {
            uint32_t ah[4][4], al[4][4], bh[2][4];
#pragma unroll
            for (int mt = 0; mt < 4; mt++) {
                const uint32_t ao = (uint32_t)(mt * 16 * ROWP + ks * 32);
                ldsm_x4(ah[mt][0], ah[mt][1], ah[mt][2], ah[mt][3], sb + aoff_hi + ao);
                ldsm_x4(al[mt][0], al[mt][1], al[mt][2], al[mt][3], sb + aoff_lo + ao);
            }
#pragma unroll
            for (int np = 0; np < 2; np++) {
                const uint32_t go = (uint32_t)(np * 16 * ROWP + ks * 32);
                ldsm_x4(bh[np][0], bh[np][1], bh[np][2], bh[np][3], sb + boff + go);
            }
            // hi pass (f32 acc), then lo pass (f16 acc, 2x rate if de-rated f32)
#pragma unroll
            for (int np = 0; np < 2; np++)
#pragma unroll
                for (int mt = 0; mt < 4; mt++) {
                    mma_f16(acc[mt][2*np+0], ah[mt], bh[np][0], bh[np][1]);
                    mma_f16(acc[mt][2*np+1], ah[mt], bh[np][2], bh[np][3]);
                }
#pragma unroll
            for (int np = 0; np < 2; np++)
#pragma unroll
                for (int mt = 0; mt < 4; mt++) {
                    mma_f16h(acc16[mt][2*np+0], al[mt], bh[np][0], bh[np][1]);
                    mma_f16h(acc16[mt][2*np+1], al[mt], bh[np][2], bh[np][3]);
                }
        }
    }

    // ---- epilogue ----
    const int erow = m0 + wm + (lane >> 2);
    const int ecol = n0 + wn + 2 * (lane & 3);
#pragma unroll
    for (int mt = 0; mt < 4; mt++) {
#pragma unroll
        for (int nt = 0; nt < 4; nt++) {
            const int col = ecol + nt * 8;
            const float bs0 = sbias[col - n0], bs1 = sbias[col - n0 + 1];
#pragma unroll
            for (int hrow = 0; hrow < 2; hrow++) {
                const int row = erow + mt * 16 + hrow * 8;
                if (row < rend) {
                    const uint32_t lr = acc16[mt][nt][hrow];
                    const float lo0 = __half2float(__ushort_as_half((unsigned short)(lr & 0xffffu)));
                    const float lo1 = __half2float(__ushort_as_half((unsigned short)(lr >> 16)));
                    float v0 = acc[mt][nt][2 * hrow + 0] + lo0 * LO_INV_SCALE + bs0;
                    float v1 = acc[mt][nt][2 * hrow + 1] + lo1 * LO_INV_SCALE + bs1;
                    size_t off = (size_t)row * NT + col;
                    if (G == 1) {
                        v0 = fmaxf(v0, 0.f);
                        v1 = fmaxf(v1, 0.f);
                        __half h0 = __float2half_rn(v0);
                        __half h1 = __float2half_rn(v1);
                        __half l0 = __float2half_rn((v0 - __half2float(h0)) * LO_SCALE);
                        __half l1 = __float2half_rn((v1 - __half2float(h1)) * LO_SCALE);
                        *(uint32_t*)(g_hhi + off) = hpack(h0, h1);
                        *(uint32_t*)(g_hlo + off) = hpack(l0, l1);
                    } else {
                        float2 o; o.x = v0; o.y = v1;
                        *(float2*)(g_partial + off) = o;
                    }
                }
            }
        }
    }
}

// ---------------- combine -----------------------------------------------------
__global__ __launch_bounds__(256) void combine_kernel(float* __restrict__ out) {
    int idx = blockIdx.x * blockDim.x + threadIdx.x;
    int n = idx >> 8;
    int cc = (idx & 255) << 2;
    if (n >= N_TOK) return;
    float w0 = g_w_of[2*n+0], w1 = g_w_of[2*n+1];
    int   r0 = g_token_row[2*n+0], r1 = g_token_row[2*n+1];
    float4 p0 = *(const float4*)(g_partial + (size_t)r0 * D_OUTF + cc);
    float4 p1 = *(const float4*)(g_partial + (size_t)r1 * D_OUTF + cc);
    float4 o;
    o.x = w0*p0.x + w1*p1.x;  o.y = w0*p0.y + w1*p1.y;
    o.z = w0*p0.z + w1*p1.z;  o.w = w0*p0.w + w1*p1.w;
    *(float4*)(out + (size_t)n * D_OUTF + cc) = o;
}

// ---------------- launcher ----------------------------------------------------
extern "C" void kernel_launch(void* const* d_in, const int* in_sizes, int n_in,
                              void* d_out, int out_size) {
    const float* x  = (const float*)d_in[0];
    const float* W1 = (const float*)d_in[1];
    const float* b1 = (const float*)d_in[2];
    const float* W2 = (const float*)d_in[3];
    const float* b2 = (const float*)d_in[4];
    const float* Wg = (const float*)d_in[5];
    const float* bg = (const float*)d_in[6];
    float* out = (float*)d_out;

    cudaFuncSetAttribute(gemm_kernel<1>, cudaFuncAttributeMaxDynamicSharedMemorySize, SMEM_DYN);
    cudaFuncSetAttribute(gemm_kernel<2>, cudaFuncAttributeMaxDynamicSharedMemorySize, SMEM_DYN);

    reset_kernel<<<1, 32>>>();
    gating_kernel<<<N_TOK / 8, 256>>>(x, Wg, bg);
    scan_kernel<<<1, 1>>>();
    place_kernel<<<N_TOK / 256, 256>>>();

    cvtx_kernel<<<(N_TOK * D_INF / 4) / 256, 256>>>(x);
    tpose_kernel<D_INF,  D_HIDF, 1><<<dim3(D_HIDF/32, D_INF/32,  NE), dim3(32, 8)>>>(W1);
    tpose_kernel<D_HIDF, D_OUTF, 2><<<dim3(D_OUTF/32, D_HIDF/32, NE), dim3(32, 8)>>>(W2);

    gemm_kernel<1><<<dim3(D_HIDF/128, 64, NE), 256, SMEM_DYN>>>(b1);
    gemm_kernel<2><<<dim3(D_OUTF/128, 64, NE), 256, SMEM_DYN>>>(b2);

    combine_kernel<<<(N_TOK * D_OUTF / 4) / 256, 256>>>(out);
}

// round 13
// speedup vs baseline: 1.8815x; 1.8815x over previous
#include <cuda_runtime.h>
#include <cuda_bf16.h>
#include <cuda_fp16.h>
#include <math.h>
#include <stdint.h>

// Problem constants
#define N_TOK  8192
#define D_INF  1024
#define D_HIDF 4096
#define D_OUTF 1024
#define NE     8
#define TOPK   2
#define NROWS  (N_TOK * TOPK)

// ---------------- scratch (__device__ globals; allocation-free rule) --------
__device__ __align__(256) __half g_xh[(size_t)N_TOK * D_INF];
__device__ __align__(256) __half g_w1t[(size_t)NE * D_HIDF * D_INF];  // [E][Nhid][Kin]
__device__ __align__(256) __half g_w2t[(size_t)NE * D_OUTF * D_HIDF]; // [E][Nout][Khid]
__device__ __align__(256) __half g_h[(size_t)NROWS * D_HIDF];
__device__ __align__(256) float g_partial[(size_t)NROWS * D_OUTF];
__device__ int   g_counts[NE];
__device__ int   g_offsets[NE + 1];
__device__ int   g_cursor[NE];
__device__ int   g_row_token[NROWS];
__device__ int   g_token_row[NROWS];
__device__ int   g_e_of[NROWS];
__device__ float g_w_of[NROWS];

// ---------------- PTX helpers (base sm_103 only; NO 'a' features) -----------
__device__ __forceinline__ uint32_t smem_u32(const void* p) {
    uint32_t a;
    asm("{ .reg .u64 t; cvta.to.shared.u64 t, %1; cvt.u32.u64 %0, t; }"
        : "=r"(a) : "l"(p));
    return a;
}
__device__ __forceinline__ void cp16(uint32_t dst, const void* src) {
    unsigned long long g = (unsigned long long)__cvta_generic_to_global(src);
    asm volatile("cp.async.cg.shared.global [%0], [%1], 16;" :: "r"(dst), "l"(g));
}
#define CP_COMMIT() asm volatile("cp.async.commit_group;" ::: "memory")
template <int Np> __device__ __forceinline__ void cp_wait() {
    asm volatile("cp.async.wait_group %0;" :: "n"(Np) : "memory");
}
__device__ __forceinline__ void ldsm_x4(uint32_t& r0, uint32_t& r1, uint32_t& r2,
                                        uint32_t& r3, uint32_t addr) {
    asm volatile("ldmatrix.sync.aligned.m8n8.x4.shared.b16 {%0,%1,%2,%3}, [%4];"
                 : "=r"(r0), "=r"(r1), "=r"(r2), "=r"(r3) : "r"(addr));
}
__device__ __forceinline__ void mma_f16(float* c, const uint32_t* a, uint32_t b0,
                                        uint32_t b1) {
    asm volatile(
        "mma.sync.aligned.m16n8k16.row.col.f32.f16.f16.f32 "
        "{%0,%1,%2,%3}, {%4,%5,%6,%7}, {%8,%9}, {%0,%1,%2,%3};"
        : "+f"(c[0]), "+f"(c[1]), "+f"(c[2]), "+f"(c[3])
        : "r"(a[0]), "r"(a[1]), "r"(a[2]), "r"(a[3]), "r"(b0), "r"(b1));
}
__device__ __forceinline__ uint32_t hpack(__half a, __half b) {
    return (uint32_t)__half_as_ushort(a) | ((uint32_t)__half_as_ushort(b) << 16);
}

// ---------------- kernel 0: reset --------------------------------------------
__global__ void reset_kernel() {
    int t = threadIdx.x;
    if (t < NE) g_counts[t] = 0;
}

// ---------------- kernel 1: gating -------------------------------------------
__global__ __launch_bounds__(256) void gating_kernel(
    const float* __restrict__ x, const float* __restrict__ Wg,
    const float* __restrict__ bg)
{
    int gwarp = (blockIdx.x * blockDim.x + threadIdx.x) >> 5;
    int lane  = threadIdx.x & 31;
    if (gwarp >= N_TOK) return;
    const float* xr = x + (size_t)gwarp * D_INF;

    float acc[NE];
#pragma unroll
    for (int e = 0; e < NE; e++) acc[e] = 0.f;
    for (int k = lane; k < D_INF; k += 32) {
        float xv = xr[k];
        const float* wgr = Wg + (size_t)k * NE;
#pragma unroll
        for (int e = 0; e < NE; e++) acc[e] = fmaf(xv, wgr[e], acc[e]);
    }
#pragma unroll
    for (int off = 16; off; off >>= 1)
#pragma unroll
        for (int e = 0; e < NE; e++)
            acc[e] += __shfl_xor_sync(0xffffffffu, acc[e], off);

    if (lane == 0) {
        float s[NE];
#pragma unroll
        for (int e = 0; e < NE; e++) s[e] = acc[e] + bg[e];
        float mx = s[0];
#pragma unroll
        for (int e = 1; e < NE; e++) mx = fmaxf(mx, s[e]);
        float p[NE], sum = 0.f;
#pragma unroll
        for (int e = 0; e < NE; e++) { p[e] = expf(s[e] - mx); sum += p[e]; }
        float inv = 1.0f / sum;
#pragma unroll
        for (int e = 0; e < NE; e++) p[e] *= inv;
        int e0 = 0;
#pragma unroll
        for (int e = 1; e < NE; e++) if (s[e] > s[e0]) e0 = e;
        int e1 = (e0 == 0) ? 1 : 0;
#pragma unroll
        for (int e = 0; e < NE; e++) if (e != e0 && s[e] > s[e1]) e1 = e;
        float denom = p[e0] + p[e1] + 1e-8f;
        int n = gwarp;
        g_e_of[2*n+0] = e0;  g_e_of[2*n+1] = e1;
        g_w_of[2*n+0] = p[e0] / denom;  g_w_of[2*n+1] = p[e1] / denom;
        atomicAdd(&g_counts[e0], 1);
        atomicAdd(&g_counts[e1], 1);
    }
}

// ---------------- kernel 2/3: scan + placement -------------------------------
__global__ void scan_kernel() {
    int o = 0;
#pragma unroll
    for (int e = 0; e < NE; e++) { g_offsets[e] = o; g_cursor[e] = o; o += g_counts[e]; }
    g_offsets[NE] = o;
}
__global__ void place_kernel() {
    int n = blockIdx.x * blockDim.x + threadIdx.x;
    if (n >= N_TOK) return;
#pragma unroll
    for (int s = 0; s < TOPK; s++) {
        int e = g_e_of[2*n+s];
        int r = atomicAdd(&g_cursor[e], 1);
        g_row_token[r] = n;
        g_token_row[2*n+s] = r;
    }
}

// ---------------- prepass: x -> fp16 -----------------------------------------
__global__ __launch_bounds__(256) void cvtx_kernel(const float* __restrict__ x) {
    size_t i = ((size_t)blockIdx.x * 256 + threadIdx.x) * 4;
    float4 v = *(const float4*)(x + i);
    uint2 hh;
    hh.x = hpack(__float2half_rn(v.x), __float2half_rn(v.y));
    hh.y = hpack(__float2half_rn(v.z), __float2half_rn(v.w));
    *(uint2*)(g_xh + i) = hh;
}

// ---------------- prepass: W [E][K][N] -> WT fp16 [E][N][K] -------------------
template <int K, int N, int WCH>
__global__ void tpose_kernel(const float* __restrict__ Wsrc) {
    __shared__ float t[32][33];
    int e  = blockIdx.z;
    int n0 = blockIdx.x * 32, k0 = blockIdx.y * 32;
    int tx = threadIdx.x, ty = threadIdx.y;  // 32 x 8
    const float* src = Wsrc + ((size_t)e * K + k0) * N + n0;
#pragma unroll
    for (int i = 0; i < 4; i++)
        t[ty + 8*i][tx] = src[(size_t)(ty + 8*i) * N + tx];
    __syncthreads();
    __half* T = (WCH == 1) ? g_w1t : g_w2t;
    size_t ob = ((size_t)e * N + n0) * K + k0;
#pragma unroll
    for (int i = 0; i < 4; i++) {
        float v = t[tx][ty + 8*i];
        T[ob + (size_t)(ty + 8*i) * K + tx] = __float2half_rn(v);
    }
}

// ---------------- grouped HMMA GEMM (fp16 1-pass, f32 acc) --------------------
// BM=128, BN=128, BK=64, 256 threads (8 warps, warp tile 64x32), 3-stage
// cp.async, 2 CTAs/SM. Stage rows: [0,128)=A, [128,256)=B; 144B pitch.
#define ROWP       144
#define STAGE_ROWS 256
#define STAGE_SZ   (STAGE_ROWS * ROWP)      // 36864
#define NSTAGE     3
#define SMEM_DYN   (NSTAGE * STAGE_SZ + 128)  // 110720

template <int G>
__global__ __launch_bounds__(256, 2) void gemm_kernel(const float* __restrict__ bias_g) {
    constexpr int KD = (G == 1) ? D_INF : D_HIDF;
    constexpr int NT = (G == 1) ? D_HIDF : D_OUTF;
    constexpr int KT = KD / 64;

    const int e    = blockIdx.z;
    const int rbeg = g_offsets[e];
    const int rend = g_offsets[e + 1];
    const int m0   = rbeg + blockIdx.y * 128;
    if (m0 >= rend) return;
    const int n0   = blockIdx.x * 128;

    __shared__ float sbias[128];
    extern __shared__ char dsm[];
    const uint32_t dynb = (smem_u32(dsm) + 127u) & ~127u;

    const int tid  = threadIdx.x;
    const int wid  = tid >> 5;
    const int lane = tid & 31;

    if (tid < 128) sbias[tid] = bias_g[(size_t)e * NT + n0 + tid];

    const __half* a_g = (G == 1) ? g_xh : g_h;
    const __half* b_g = (G == 1) ? g_w1t : g_w2t;

    // ---- loader geometry: 256 rows / 256 threads, one row each --------------
    const __half* gsrc;
    uint32_t dstoff = (uint32_t)(tid * ROWP);
    if (tid < 128) {                        // A row
        int gr = m0 + tid;
        if (gr >= rend) gr = rbeg;          // valid garbage row; epilogue masks
        size_t rowb = (G == 1) ? (size_t)g_row_token[gr] * KD : (size_t)gr * KD;
        gsrc = a_g + rowb;
    } else {                                // B row
        const int br = tid - 128;           // 0..127
        gsrc = b_g + ((size_t)e * NT + n0 + br) * KD;
    }

    auto load_stage = [&](int kt, int stg) {
        const uint32_t sb = dynb + (uint32_t)stg * STAGE_SZ;
        const __half* src = gsrc + kt * 64;
        const uint32_t dst = sb + dstoff;
#pragma unroll
        for (int c = 0; c < 8; c++) cp16(dst + c * 16, src + c * 8);
        CP_COMMIT();
    };

    // ---- fragment address bases ----
    const int wm = (wid >> 2) * 64;     // warp M offset: 0,64
    const int wn = (wid & 3) * 32;      // warp N offset: 0,32,64,96
    const int mtx = lane >> 3;          // ldmatrix matrix id 0..3
    const int inr = lane & 7;
    // A x4 tile: matrices {m0-7 k0, m8-15 k0, m0-7 k8, m8-15 k8}
    const uint32_t aoff = (uint32_t)((wm + (mtx & 1) * 8 + inr) * ROWP + (mtx >> 1) * 16);
    // B x4 tile: matrices {n0-7 k0, n0-7 k8, n8-15 k0, n8-15 k8}
    const uint32_t boff = (uint32_t)((128 + wn + (mtx >> 1) * 8 + inr) * ROWP + (mtx & 1) * 16);

    float acc[4][4][4];
#pragma unroll
    for (int i = 0; i < 4; i++)
#pragma unroll
        for (int j = 0; j < 4; j++)
#pragma unroll
            for (int q = 0; q < 4; q++) acc[i][j][q] = 0.f;

    load_stage(0, 0);
    load_stage(1, 1);

    for (int kt = 0; kt < KT; kt++) {
        if (kt == KT - 1) cp_wait<0>(); else cp_wait<1>();
        __syncthreads();   // stage kt visible; stage kt-2's consumers done
        if (kt + 2 < KT) load_stage(kt + 2, (kt + 2) % NSTAGE);

        const uint32_t sb = dynb + (uint32_t)(kt % NSTAGE) * STAGE_SZ;
#pragma unroll
        for (int ks = 0; ks < 4; ks++) {
            uint32_t ah[4][4], bh[2][4];
#pragma unroll
            for (int mt = 0; mt < 4; mt++) {
                const uint32_t ao = (uint32_t)(mt * 16 * ROWP + ks * 32);
                ldsm_x4(ah[mt][0], ah[mt][1], ah[mt][2], ah[mt][3], sb + aoff + ao);
            }
#pragma unroll
            for (int np = 0; np < 2; np++) {
                const uint32_t go = (uint32_t)(np * 16 * ROWP + ks * 32);
                ldsm_x4(bh[np][0], bh[np][1], bh[np][2], bh[np][3], sb + boff + go);
            }
#pragma unroll
            for (int np = 0; np < 2; np++)
#pragma unroll
                for (int mt = 0; mt < 4; mt++) {
                    mma_f16(acc[mt][2*np+0], ah[mt], bh[np][0], bh[np][1]);
                    mma_f16(acc[mt][2*np+1], ah[mt], bh[np][2], bh[np][3]);
                }
        }
    }

    // ---- epilogue ----
    const int erow = m0 + wm + (lane >> 2);
    const int ecol = n0 + wn + 2 * (lane & 3);
#pragma unroll
    for (int mt = 0; mt < 4; mt++) {
#pragma unroll
        for (int nt = 0; nt < 4; nt++) {
            const int col = ecol + nt * 8;
            const float bs0 = sbias[col - n0], bs1 = sbias[col - n0 + 1];
#pragma unroll
            for (int hrow = 0; hrow < 2; hrow++) {
                const int row = erow + mt * 16 + hrow * 8;
                if (row < rend) {
                    float v0 = acc[mt][nt][2 * hrow + 0] + bs0;
                    float v1 = acc[mt][nt][2 * hrow + 1] + bs1;
                    size_t off = (size_t)row * NT + col;
                    if (G == 1) {
                        v0 = fmaxf(v0, 0.f);
                        v1 = fmaxf(v1, 0.f);
                        *(uint32_t*)(g_h + off) =
                            hpack(__float2half_rn(v0), __float2half_rn(v1));
                    } else {
                        float2 o; o.x = v0; o.y = v1;
                        *(float2*)(g_partial + off) = o;
                    }
                }
            }
        }
    }
}

// ---------------- combine -----------------------------------------------------
__global__ __launch_bounds__(256) void combine_kernel(float* __restrict__ out) {
    int idx = blockIdx.x * blockDim.x + threadIdx.x;
    int n = idx >> 8;
    int cc = (idx & 255) << 2;
    if (n >= N_TOK) return;
    float w0 = g_w_of[2*n+0], w1 = g_w_of[2*n+1];
    int   r0 = g_token_row[2*n+0], r1 = g_token_row[2*n+1];
    float4 p0 = *(const float4*)(g_partial + (size_t)r0 * D_OUTF + cc);
    float4 p1 = *(const float4*)(g_partial + (size_t)r1 * D_OUTF + cc);
    float4 o;
    o.x = w0*p0.x + w1*p1.x;  o.y = w0*p0.y + w1*p1.y;
    o.z = w0*p0.z + w1*p1.z;  o.w = w0*p0.w + w1*p1.w;
    *(float4*)(out + (size_t)n * D_OUTF + cc) = o;
}

// ---------------- launcher ----------------------------------------------------
extern "C" void kernel_launch(void* const* d_in, const int* in_sizes, int n_in,
                              void* d_out, int out_size) {
    const float* x  = (const float*)d_in[0];
    const float* W1 = (const float*)d_in[1];
    const float* b1 = (const float*)d_in[2];
    const float* W2 = (const float*)d_in[3];
    const float* b2 = (const float*)d_in[4];
    const float* Wg = (const float*)d_in[5];
    const float* bg = (const float*)d_in[6];
    float* out = (float*)d_out;

    cudaFuncSetAttribute(gemm_kernel<1>, cudaFuncAttributeMaxDynamicSharedMemorySize, SMEM_DYN);
    cudaFuncSetAttribute(gemm_kernel<2>, cudaFuncAttributeMaxDynamicSharedMemorySize, SMEM_DYN);

    reset_kernel<<<1, 32>>>();
    gating_kernel<<<N_TOK / 8, 256>>>(x, Wg, bg);
    scan_kernel<<<1, 1>>>();
    place_kernel<<<N_TOK / 256, 256>>>();

    cvtx_kernel<<<(N_TOK * D_INF / 4) / 256, 256>>>(x);
    tpose_kernel<D_INF,  D_HIDF, 1><<<dim3(D_HIDF/32, D_INF/32,  NE), dim3(32, 8)>>>(W1);
    tpose_kernel<D_HIDF, D_OUTF, 2><<<dim3(D_OUTF/32, D_HIDF/32, NE), dim3(32, 8)>>>(W2);

    gemm_kernel<1><<<dim3(D_HIDF/128, 64, NE), 256, SMEM_DYN>>>(b1);
    gemm_kernel<2><<<dim3(D_OUTF/128, 64, NE), 256, SMEM_DYN>>>(b2);

    combine_kernel<<<(N_TOK * D_OUTF / 4) / 256, 256>>>(out);
}